// round 2
// baseline (speedup 1.0000x reference)
#include <cuda_runtime.h>

#define D 128
#define MAXN 100000

// Scratch (allocation-free rule: __device__ globals). float4 => 16B alignment
// guaranteed for vector loads/stores and red.global.add.v4.f32.
__device__ float4 g_h4[MAXN * 32];   // linear-layer output of current layer
__device__ float4 g_t4[MAXN * 32];   // layer-1 aggregated output
__device__ int    g_deg[MAXN];
__device__ float  g_dinv[MAXN];

// ---------------------------------------------------------------------------
// Degree computation
// ---------------------------------------------------------------------------
__global__ void zero_deg(int n) {
    int i = blockIdx.x * blockDim.x + threadIdx.x;
    if (i < n) g_deg[i] = 0;
}

__global__ void count_deg(const int* __restrict__ dst, int E) {
    int e = blockIdx.x * blockDim.x + threadIdx.x;
    if (e < E) atomicAdd(&g_deg[dst[e]], 1);
}

__global__ void calc_dinv(int n) {
    int i = blockIdx.x * blockDim.x + threadIdx.x;
    if (i < n) g_dinv[i] = rsqrtf((float)(g_deg[i] + 1));  // +1 self-loop
}

// ---------------------------------------------------------------------------
// NT GEMM: H[i][j] = sum_k X[i][k] * W[j][k]   (K = 128, chunked by 32)
// Fused epilogue: Out[i][j] = H[i][j]*dinv[i]^2 + bias[j] + pert[i][j]
// (self-loop contribution + bias + perturbation; edge messages added later)
// 128 rows/block, 256 threads, 8x8 register tile per thread.
// ---------------------------------------------------------------------------
__global__ __launch_bounds__(256, 2)
void gemm_nt_fused(const float* __restrict__ X,
                   const float* __restrict__ W,
                   const float* __restrict__ bias,
                   const float* __restrict__ pert,
                   float* __restrict__ H,
                   float* __restrict__ Out,
                   int M) {
    __shared__ float As[128][33];   // [row][k-within-chunk], +1 pad
    __shared__ float Bs[128][33];   // [out-col][k-within-chunk]

    int tid  = threadIdx.x;
    int row0 = blockIdx.x * 128;
    int trow = tid >> 4;   // 0..15
    int tcol = tid & 15;   // 0..15

    float acc[8][8];
    #pragma unroll
    for (int i = 0; i < 8; i++)
        #pragma unroll
        for (int j = 0; j < 8; j++) acc[i][j] = 0.f;

    for (int kc = 0; kc < 4; kc++) {        // 4 chunks of 32 k
        // Load A chunk (128 rows x 32 k) and W chunk (128 cols x 32 k).
        #pragma unroll
        for (int it = 0; it < 4; it++) {
            int idx = it * 256 + tid;       // 0..1023 float4s
            int r  = idx >> 3;              // 0..127
            int k4 = idx & 7;               // 0..7 (float4 within 32 k)
            int grow = row0 + r;
            float4 a = make_float4(0.f, 0.f, 0.f, 0.f);
            if (grow < M)
                a = ((const float4*)(X + (size_t)grow * D + kc * 32))[k4];
            As[r][k4 * 4 + 0] = a.x; As[r][k4 * 4 + 1] = a.y;
            As[r][k4 * 4 + 2] = a.z; As[r][k4 * 4 + 3] = a.w;
            float4 b = ((const float4*)(W + (size_t)r * D + kc * 32))[k4];
            Bs[r][k4 * 4 + 0] = b.x; Bs[r][k4 * 4 + 1] = b.y;
            Bs[r][k4 * 4 + 2] = b.z; Bs[r][k4 * 4 + 3] = b.w;
        }
        __syncthreads();

        #pragma unroll
        for (int k = 0; k < 32; k++) {
            float a[8], b[8];
            #pragma unroll
            for (int i = 0; i < 8; i++) a[i] = As[trow * 8 + i][k];
            #pragma unroll
            for (int j = 0; j < 8; j++) b[j] = Bs[tcol * 8 + j][k];
            #pragma unroll
            for (int i = 0; i < 8; i++)
                #pragma unroll
                for (int j = 0; j < 8; j++) acc[i][j] += a[i] * b[j];
        }
        __syncthreads();
    }

    // bias slice for this thread's 8 columns
    float bv[8];
    #pragma unroll
    for (int j = 0; j < 8; j++) bv[j] = bias[tcol * 8 + j];

    #pragma unroll
    for (int i = 0; i < 8; i++) {
        int grow = row0 + trow * 8 + i;
        if (grow < M) {
            float s = g_dinv[grow];
            s = s * s;
            size_t off = (size_t)grow * D + tcol * 8;
            float4* hp = (float4*)(H + off);
            float4* op = (float4*)(Out + off);
            const float4* pp = (const float4*)(pert + off);
            float4 h0 = make_float4(acc[i][0], acc[i][1], acc[i][2], acc[i][3]);
            float4 h1 = make_float4(acc[i][4], acc[i][5], acc[i][6], acc[i][7]);
            hp[0] = h0; hp[1] = h1;
            float4 p0 = pp[0], p1 = pp[1];
            float4 o0 = make_float4(h0.x * s + bv[0] + p0.x, h0.y * s + bv[1] + p0.y,
                                    h0.z * s + bv[2] + p0.z, h0.w * s + bv[3] + p0.w);
            float4 o1 = make_float4(h1.x * s + bv[4] + p1.x, h1.y * s + bv[5] + p1.y,
                                    h1.z * s + bv[6] + p1.z, h1.w * s + bv[7] + p1.w);
            op[0] = o0; op[1] = o1;
        }
    }
}

// ---------------------------------------------------------------------------
// Edge scatter: out[dst] += h[src] * dinv[src] * dinv[dst]
// One warp per edge; each lane handles one float4 (32 lanes x 4 = 128 dims).
// ---------------------------------------------------------------------------
__global__ __launch_bounds__(256)
void scatter_edges(const int* __restrict__ src,
                   const int* __restrict__ dst,
                   const float4* __restrict__ h,
                   float* __restrict__ out,
                   int E) {
    long long t = (long long)blockIdx.x * blockDim.x + threadIdx.x;
    int e = (int)(t >> 5);
    if (e >= E) return;
    int lane = (int)(t & 31);

    int s = src[e];
    int d = dst[e];
    float w = g_dinv[s] * g_dinv[d];

    float4 v = h[(size_t)s * 32 + lane];
    float* p = out + (size_t)d * D + lane * 4;
    asm volatile("red.global.add.v4.f32 [%0], {%1, %2, %3, %4};"
                 :: "l"(p), "f"(v.x * w), "f"(v.y * w), "f"(v.z * w), "f"(v.w * w)
                 : "memory");
}

// ---------------------------------------------------------------------------
// Launch
// Inputs: x[N*D], edge_index[2*E], perturb_first[N*D], perturb_last[N*D],
//         W1[D*D], b1[D], W2[D*D], b2[D]   -> out[N*D]
// ---------------------------------------------------------------------------
extern "C" void kernel_launch(void* const* d_in, const int* in_sizes, int n_in,
                              void* d_out, int out_size) {
    const float* x  = (const float*)d_in[0];
    const int*   ei = (const int*)d_in[1];
    const float* pf = (const float*)d_in[2];
    const float* pl = (const float*)d_in[3];
    const float* W1 = (const float*)d_in[4];
    const float* b1 = (const float*)d_in[5];
    const float* W2 = (const float*)d_in[6];
    const float* b2 = (const float*)d_in[7];
    float* out = (float*)d_out;

    int N = in_sizes[0] / D;
    int E = in_sizes[1] / 2;
    const int* src = ei;
    const int* dst = ei + E;

    float4* Gh; cudaGetSymbolAddress((void**)&Gh, g_h4);
    float4* Gt; cudaGetSymbolAddress((void**)&Gt, g_t4);

    int tb = 256;

    // Degrees + normalization
    zero_deg<<<(N + tb - 1) / tb, tb>>>(N);
    count_deg<<<(E + tb - 1) / tb, tb>>>(dst, E);
    calc_dinv<<<(N + tb - 1) / tb, tb>>>(N);

    int gemm_grid = (N + 127) / 128;
    long long sc_threads = (long long)E * 32;
    int sc_grid = (int)((sc_threads + tb - 1) / tb);

    // Layer 1: h1 = x @ W1^T ; t = h1*dinv^2 + b1 + pf ; t[dst] += h1[src]*norm
    gemm_nt_fused<<<gemm_grid, tb>>>(x, W1, b1, pf, (float*)Gh, (float*)Gt, N);
    scatter_edges<<<sc_grid, tb>>>(src, dst, Gh, (float*)Gt, E);

    // Layer 2: h2 = t @ W2^T ; out = h2*dinv^2 + b2 + pl ; out[dst] += h2[src]*norm
    gemm_nt_fused<<<gemm_grid, tb>>>((const float*)Gt, W2, b2, pl, (float*)Gh, out, N);
    scatter_edges<<<sc_grid, tb>>>(src, dst, Gh, out, E);
}

// round 3
// speedup vs baseline: 1.5283x; 1.5283x over previous
#include <cuda_runtime.h>

#define D 128
#define MAXN 100000
#define MAXE 1664000
#define SCAN_B 1024

// Scratch (allocation-free rule: __device__ globals). float4 => 16B alignment.
__device__ float4 g_h4[MAXN * 32];     // linear-layer output of current layer
__device__ float4 g_t4[MAXN * 32];     // layer-1 aggregated output
__device__ int    g_deg[MAXN];
__device__ float  g_dinv[MAXN];
__device__ int    g_off[MAXN];         // CSR row start (by dst)
__device__ int    g_cur[MAXN];         // fill cursors
__device__ int    g_csrc[MAXE];        // CSR: src node per edge, grouped by dst
__device__ int    g_bsum[(MAXN + SCAN_B - 1) / SCAN_B];  // scan block sums

// ---------------------------------------------------------------------------
// Degree histogram
// ---------------------------------------------------------------------------
__global__ void zero_deg(int n) {
    int i = blockIdx.x * blockDim.x + threadIdx.x;
    if (i < n) g_deg[i] = 0;
}

__global__ void count_deg(const int* __restrict__ dst, int E) {
    int e = blockIdx.x * blockDim.x + threadIdx.x;
    if (e < E) atomicAdd(&g_deg[dst[e]], 1);
}

// ---------------------------------------------------------------------------
// Exclusive scan of g_deg -> g_off (3 kernels), + dinv + cursor init
// ---------------------------------------------------------------------------
__global__ __launch_bounds__(SCAN_B)
void scan_block_sums(int n) {
    __shared__ int sh[SCAN_B];
    int i = blockIdx.x * SCAN_B + threadIdx.x;
    sh[threadIdx.x] = (i < n) ? g_deg[i] : 0;
    __syncthreads();
    for (int off = SCAN_B / 2; off > 0; off >>= 1) {
        if (threadIdx.x < off) sh[threadIdx.x] += sh[threadIdx.x + off];
        __syncthreads();
    }
    if (threadIdx.x == 0) g_bsum[blockIdx.x] = sh[0];
}

__global__ void scan_spine(int nb) {
    if (threadIdx.x == 0) {
        int acc = 0;
        for (int b = 0; b < nb; b++) {
            int v = g_bsum[b];
            g_bsum[b] = acc;
            acc += v;
        }
    }
}

__global__ __launch_bounds__(SCAN_B)
void scan_finish(int n) {
    __shared__ int sh[SCAN_B];
    int i = blockIdx.x * SCAN_B + threadIdx.x;
    int v = (i < n) ? g_deg[i] : 0;
    sh[threadIdx.x] = v;
    __syncthreads();
    // Hillis-Steele inclusive scan
    for (int off = 1; off < SCAN_B; off <<= 1) {
        int t = (threadIdx.x >= off) ? sh[threadIdx.x - off] : 0;
        __syncthreads();
        sh[threadIdx.x] += t;
        __syncthreads();
    }
    if (i < n) {
        int excl = sh[threadIdx.x] - v + g_bsum[blockIdx.x];
        g_off[i] = excl;
        g_cur[i] = excl;
        g_dinv[i] = rsqrtf((float)(v + 1));   // +1 self-loop
    }
}

// ---------------------------------------------------------------------------
// CSR fill: place src of each edge into its dst bucket
// ---------------------------------------------------------------------------
__global__ void fill_csr(const int* __restrict__ src,
                         const int* __restrict__ dst, int E) {
    int e = blockIdx.x * blockDim.x + threadIdx.x;
    if (e < E) {
        int pos = atomicAdd(&g_cur[dst[e]], 1);
        g_csrc[pos] = src[e];
    }
}

// ---------------------------------------------------------------------------
// NT GEMM: H[i][j] = sum_k X[i][k] * W[j][k]   (K = 128, chunked by 32)
// Writes only H; all epilogue work moved into the gather kernel.
// 128 rows/block, 256 threads, 8x8 register tile per thread.
// ---------------------------------------------------------------------------
__global__ __launch_bounds__(256, 2)
void gemm_nt(const float* __restrict__ X,
             const float* __restrict__ W,
             float4* __restrict__ H,
             int M) {
    __shared__ float As[128][33];   // [row][k-within-chunk], +1 pad
    __shared__ float Bs[128][33];   // [out-col][k-within-chunk]

    int tid  = threadIdx.x;
    int row0 = blockIdx.x * 128;
    int trow = tid >> 4;   // 0..15
    int tcol = tid & 15;   // 0..15

    float acc[8][8];
    #pragma unroll
    for (int i = 0; i < 8; i++)
        #pragma unroll
        for (int j = 0; j < 8; j++) acc[i][j] = 0.f;

    for (int kc = 0; kc < 4; kc++) {        // 4 chunks of 32 k
        #pragma unroll
        for (int it = 0; it < 4; it++) {
            int idx = it * 256 + tid;       // 0..1023 float4s
            int r  = idx >> 3;              // 0..127
            int k4 = idx & 7;               // 0..7
            int grow = row0 + r;
            float4 a = make_float4(0.f, 0.f, 0.f, 0.f);
            if (grow < M)
                a = ((const float4*)(X + (size_t)grow * D + kc * 32))[k4];
            As[r][k4 * 4 + 0] = a.x; As[r][k4 * 4 + 1] = a.y;
            As[r][k4 * 4 + 2] = a.z; As[r][k4 * 4 + 3] = a.w;
            float4 b = ((const float4*)(W + (size_t)r * D + kc * 32))[k4];
            Bs[r][k4 * 4 + 0] = b.x; Bs[r][k4 * 4 + 1] = b.y;
            Bs[r][k4 * 4 + 2] = b.z; Bs[r][k4 * 4 + 3] = b.w;
        }
        __syncthreads();

        #pragma unroll
        for (int k = 0; k < 32; k++) {
            float a[8], b[8];
            #pragma unroll
            for (int i = 0; i < 8; i++) a[i] = As[trow * 8 + i][k];
            #pragma unroll
            for (int j = 0; j < 8; j++) b[j] = Bs[tcol * 8 + j][k];
            #pragma unroll
            for (int i = 0; i < 8; i++)
                #pragma unroll
                for (int j = 0; j < 8; j++) acc[i][j] += a[i] * b[j];
        }
        __syncthreads();
    }

    #pragma unroll
    for (int i = 0; i < 8; i++) {
        int grow = row0 + trow * 8 + i;
        if (grow < M) {
            float4* hp = (float4*)((float*)H + (size_t)grow * D + tcol * 8);
            hp[0] = make_float4(acc[i][0], acc[i][1], acc[i][2], acc[i][3]);
            hp[1] = make_float4(acc[i][4], acc[i][5], acc[i][6], acc[i][7]);
        }
    }
}

// ---------------------------------------------------------------------------
// Pull-mode aggregation (no atomics):
// out[i] = dinv[i] * sum_{e in CSR[i]} dinv[src_e] * h[src_e]
//        + dinv[i]^2 * h[i] + bias + pert[i]
// One warp per dst node; lane owns one float4 (32 x 4 = 128 dims).
// ---------------------------------------------------------------------------
__global__ __launch_bounds__(256)
void gather_aggregate(const float4* __restrict__ h,
                      const float* __restrict__ bias,
                      const float4* __restrict__ pert,
                      float4* __restrict__ out,
                      int N) {
    long long t = (long long)blockIdx.x * blockDim.x + threadIdx.x;
    int i = (int)(t >> 5);
    if (i >= N) return;
    int lane = (int)(t & 31);

    int start = g_off[i];
    int deg   = g_deg[i];

    float4 acc = make_float4(0.f, 0.f, 0.f, 0.f);
    int j = 0;
    // unroll-by-2 to expose MLP on the dependent idx->row loads
    for (; j + 2 <= deg; j += 2) {
        int s0 = g_csrc[start + j];
        int s1 = g_csrc[start + j + 1];
        float w0 = g_dinv[s0];
        float w1 = g_dinv[s1];
        float4 v0 = h[(size_t)s0 * 32 + lane];
        float4 v1 = h[(size_t)s1 * 32 + lane];
        acc.x += w0 * v0.x + w1 * v1.x;
        acc.y += w0 * v0.y + w1 * v1.y;
        acc.z += w0 * v0.z + w1 * v1.z;
        acc.w += w0 * v0.w + w1 * v1.w;
    }
    if (j < deg) {
        int s0 = g_csrc[start + j];
        float w0 = g_dinv[s0];
        float4 v0 = h[(size_t)s0 * 32 + lane];
        acc.x += w0 * v0.x; acc.y += w0 * v0.y;
        acc.z += w0 * v0.z; acc.w += w0 * v0.w;
    }

    float di = g_dinv[i];
    float d2 = di * di;
    float4 hs = h[(size_t)i * 32 + lane];
    float4 bv = ((const float4*)bias)[lane];
    float4 pv = pert[(size_t)i * 32 + lane];

    out[(size_t)i * 32 + lane] = make_float4(
        di * acc.x + d2 * hs.x + bv.x + pv.x,
        di * acc.y + d2 * hs.y + bv.y + pv.y,
        di * acc.z + d2 * hs.z + bv.z + pv.z,
        di * acc.w + d2 * hs.w + bv.w + pv.w);
}

// ---------------------------------------------------------------------------
// Launch
// Inputs: x[N*D], edge_index[2*E], perturb_first[N*D], perturb_last[N*D],
//         W1[D*D], b1[D], W2[D*D], b2[D]   -> out[N*D]
// ---------------------------------------------------------------------------
extern "C" void kernel_launch(void* const* d_in, const int* in_sizes, int n_in,
                              void* d_out, int out_size) {
    const float* x  = (const float*)d_in[0];
    const int*   ei = (const int*)d_in[1];
    const float* pf = (const float*)d_in[2];
    const float* pl = (const float*)d_in[3];
    const float* W1 = (const float*)d_in[4];
    const float* b1 = (const float*)d_in[5];
    const float* W2 = (const float*)d_in[6];
    const float* b2 = (const float*)d_in[7];
    float* out = (float*)d_out;

    int N = in_sizes[0] / D;
    int E = in_sizes[1] / 2;
    const int* src = ei;
    const int* dst = ei + E;

    float4* Gh; cudaGetSymbolAddress((void**)&Gh, g_h4);
    float4* Gt; cudaGetSymbolAddress((void**)&Gt, g_t4);

    int tb = 256;
    int nscan = (N + SCAN_B - 1) / SCAN_B;

    // Degrees + CSR + normalization
    zero_deg<<<(N + tb - 1) / tb, tb>>>(N);
    count_deg<<<(E + tb - 1) / tb, tb>>>(dst, E);
    scan_block_sums<<<nscan, SCAN_B>>>(N);
    scan_spine<<<1, 32>>>(nscan);
    scan_finish<<<nscan, SCAN_B>>>(N);
    fill_csr<<<(E + tb - 1) / tb, tb>>>(src, dst, E);

    int gemm_grid = (N + 127) / 128;
    int agg_grid  = (int)(((long long)N * 32 + tb - 1) / tb);

    // Layer 1: h1 = x @ W1^T ; t = aggregate(h1) + b1 + pf
    gemm_nt<<<gemm_grid, tb>>>(x, W1, Gh, N);
    gather_aggregate<<<agg_grid, tb>>>(Gh, b1, (const float4*)pf, Gt, N);

    // Layer 2: h2 = t @ W2^T ; out = aggregate(h2) + b2 + pl
    gemm_nt<<<gemm_grid, tb>>>((const float*)Gt, W2, Gh, N);
    gather_aggregate<<<agg_grid, tb>>>(Gh, b2, (const float4*)pl, (float4*)out, N);
}

// round 4
// speedup vs baseline: 1.9016x; 1.2443x over previous
#include <cuda_runtime.h>

#define D 128
#define MAXN 100000
#define MAXE 1664000
#define SCAN_B 1024

// Scratch (allocation-free rule: __device__ globals). float4 => 16B alignment.
__device__ float4 g_h4[MAXN * 32];     // scaled linear output: dinv[i] * (x W^T)[i]
__device__ float4 g_t4[MAXN * 32];     // layer-1 aggregated output
__device__ int    g_deg[MAXN];
__device__ float  g_dinv[MAXN];
__device__ int    g_off[MAXN];         // CSR row start (by dst)
__device__ int    g_cur[MAXN];         // fill cursors
__device__ int    g_csrc[MAXE];        // CSR: src node per edge, grouped by dst
__device__ int    g_bsum[(MAXN + SCAN_B - 1) / SCAN_B];  // scan block sums

// ---------------------------------------------------------------------------
// Degree histogram
// ---------------------------------------------------------------------------
__global__ void zero_deg(int n) {
    int i = blockIdx.x * blockDim.x + threadIdx.x;
    if (i < n) g_deg[i] = 0;
}

__global__ void count_deg(const int* __restrict__ dst, int E) {
    int e = blockIdx.x * blockDim.x + threadIdx.x;
    if (e < E) atomicAdd(&g_deg[dst[e]], 1);
}

// ---------------------------------------------------------------------------
// Exclusive scan of g_deg -> g_off (3 kernels), + dinv + cursor init
// ---------------------------------------------------------------------------
__global__ __launch_bounds__(SCAN_B)
void scan_block_sums(int n) {
    __shared__ int sh[SCAN_B];
    int i = blockIdx.x * SCAN_B + threadIdx.x;
    sh[threadIdx.x] = (i < n) ? g_deg[i] : 0;
    __syncthreads();
    for (int off = SCAN_B / 2; off > 0; off >>= 1) {
        if (threadIdx.x < off) sh[threadIdx.x] += sh[threadIdx.x + off];
        __syncthreads();
    }
    if (threadIdx.x == 0) g_bsum[blockIdx.x] = sh[0];
}

// Single warp: exclusive-scan g_bsum in place (nb <= 128 chunks of 32)
__global__ void scan_spine(int nb) {
    int lane = threadIdx.x;
    int acc = 0;
    for (int base = 0; base < nb; base += 32) {
        int idx = base + lane;
        int orig = (idx < nb) ? g_bsum[idx] : 0;
        int v = orig;
        #pragma unroll
        for (int off = 1; off < 32; off <<= 1) {
            int t = __shfl_up_sync(0xffffffffu, v, off);
            if (lane >= off) v += t;
        }
        int tot = __shfl_sync(0xffffffffu, v, 31);
        if (idx < nb) g_bsum[idx] = v - orig + acc;
        acc += tot;
    }
}

__global__ __launch_bounds__(SCAN_B)
void scan_finish(int n) {
    __shared__ int sh[SCAN_B];
    int i = blockIdx.x * SCAN_B + threadIdx.x;
    int v = (i < n) ? g_deg[i] : 0;
    sh[threadIdx.x] = v;
    __syncthreads();
    // Hillis-Steele inclusive scan
    for (int off = 1; off < SCAN_B; off <<= 1) {
        int t = (threadIdx.x >= off) ? sh[threadIdx.x - off] : 0;
        __syncthreads();
        sh[threadIdx.x] += t;
        __syncthreads();
    }
    if (i < n) {
        int excl = sh[threadIdx.x] - v + g_bsum[blockIdx.x];
        g_off[i] = excl;
        g_cur[i] = excl;
        g_dinv[i] = rsqrtf((float)(v + 1));   // +1 self-loop
    }
}

// ---------------------------------------------------------------------------
// CSR fill: place src of each edge into its dst bucket
// ---------------------------------------------------------------------------
__global__ void fill_csr(const int* __restrict__ src,
                         const int* __restrict__ dst, int E) {
    int e = blockIdx.x * blockDim.x + threadIdx.x;
    if (e < E) {
        int pos = atomicAdd(&g_cur[dst[e]], 1);
        g_csrc[pos] = src[e];
    }
}

// ---------------------------------------------------------------------------
// NT GEMM: H[i][j] = dinv[i] * sum_k X[i][k] * W[j][k]   (K = 128, chunks of 32)
// k-major smem tiles (pad 132: conflict-free STS + 16B-aligned rows) so the
// inner loop is 4x LDS.128 + 64 FFMA per k.
// 128 rows/block, 256 threads, 8x8 register tile per thread.
// ---------------------------------------------------------------------------
__global__ __launch_bounds__(256, 2)
void gemm_nt(const float* __restrict__ X,
             const float* __restrict__ W,
             float4* __restrict__ H,
             int M) {
    __shared__ float As[32][132];   // [k][row]
    __shared__ float Bs[32][132];   // [k][out-col]

    int tid  = threadIdx.x;
    int row0 = blockIdx.x * 128;
    int trow = tid >> 4;   // 0..15
    int tcol = tid & 15;   // 0..15

    float acc[8][8];
    #pragma unroll
    for (int i = 0; i < 8; i++)
        #pragma unroll
        for (int j = 0; j < 8; j++) acc[i][j] = 0.f;

    for (int kc = 0; kc < 4; kc++) {        // 4 chunks of 32 k
        #pragma unroll
        for (int it = 0; it < 4; it++) {
            int idx = it * 256 + tid;       // 0..1023 float4s per operand
            int r  = idx >> 3;              // 0..127 (row / out-col)
            int k4 = idx & 7;               // float4 index within 32-k chunk
            int grow = row0 + r;
            float4 a = make_float4(0.f, 0.f, 0.f, 0.f);
            if (grow < M)
                a = ((const float4*)(X + (size_t)grow * D + kc * 32))[k4];
            int kk = k4 * 4;
            As[kk + 0][r] = a.x; As[kk + 1][r] = a.y;
            As[kk + 2][r] = a.z; As[kk + 3][r] = a.w;
            float4 b = ((const float4*)(W + (size_t)r * D + kc * 32))[k4];
            Bs[kk + 0][r] = b.x; Bs[kk + 1][r] = b.y;
            Bs[kk + 2][r] = b.z; Bs[kk + 3][r] = b.w;
        }
        __syncthreads();

        #pragma unroll
        for (int k = 0; k < 32; k++) {
            float4 a0 = *(const float4*)&As[k][trow * 8];
            float4 a1 = *(const float4*)&As[k][trow * 8 + 4];
            float4 b0 = *(const float4*)&Bs[k][tcol * 8];
            float4 b1 = *(const float4*)&Bs[k][tcol * 8 + 4];
            float a[8] = {a0.x, a0.y, a0.z, a0.w, a1.x, a1.y, a1.z, a1.w};
            float b[8] = {b0.x, b0.y, b0.z, b0.w, b1.x, b1.y, b1.z, b1.w};
            #pragma unroll
            for (int i = 0; i < 8; i++)
                #pragma unroll
                for (int j = 0; j < 8; j++) acc[i][j] += a[i] * b[j];
        }
        __syncthreads();
    }

    #pragma unroll
    for (int i = 0; i < 8; i++) {
        int grow = row0 + trow * 8 + i;
        if (grow < M) {
            float di = g_dinv[grow];
            float4* hp = (float4*)((float*)H + (size_t)grow * D + tcol * 8);
            hp[0] = make_float4(di * acc[i][0], di * acc[i][1],
                                di * acc[i][2], di * acc[i][3]);
            hp[1] = make_float4(di * acc[i][4], di * acc[i][5],
                                di * acc[i][6], di * acc[i][7]);
        }
    }
}

// ---------------------------------------------------------------------------
// Pull-mode aggregation (no atomics). h is pre-scaled by dinv[src], so:
// out[i] = dinv[i] * ( sum_{e in CSR[i]} h[src_e] + h[i] ) + bias + pert[i]
// One warp per dst node; lane owns one float4 (32 x 4 = 128 dims).
// ---------------------------------------------------------------------------
__global__ __launch_bounds__(256)
void gather_aggregate(const float4* __restrict__ h,
                      const float* __restrict__ bias,
                      const float4* __restrict__ pert,
                      float4* __restrict__ out,
                      int N) {
    long long t = (long long)blockIdx.x * blockDim.x + threadIdx.x;
    int i = (int)(t >> 5);
    if (i >= N) return;
    int lane = (int)(t & 31);

    int start = g_off[i];
    int deg   = g_deg[i];

    float4 acc = h[(size_t)i * 32 + lane];   // self-loop term (pre-scaled)
    int j = 0;
    for (; j + 2 <= deg; j += 2) {
        int s0 = g_csrc[start + j];
        int s1 = g_csrc[start + j + 1];
        float4 v0 = h[(size_t)s0 * 32 + lane];
        float4 v1 = h[(size_t)s1 * 32 + lane];
        acc.x += v0.x + v1.x;
        acc.y += v0.y + v1.y;
        acc.z += v0.z + v1.z;
        acc.w += v0.w + v1.w;
    }
    if (j < deg) {
        int s0 = g_csrc[start + j];
        float4 v0 = h[(size_t)s0 * 32 + lane];
        acc.x += v0.x; acc.y += v0.y; acc.z += v0.z; acc.w += v0.w;
    }

    float di = g_dinv[i];
    float4 bv = ((const float4*)bias)[lane];
    float4 pv = pert[(size_t)i * 32 + lane];

    out[(size_t)i * 32 + lane] = make_float4(
        di * acc.x + bv.x + pv.x,
        di * acc.y + bv.y + pv.y,
        di * acc.z + bv.z + pv.z,
        di * acc.w + bv.w + pv.w);
}

// ---------------------------------------------------------------------------
// Launch
// Inputs: x[N*D], edge_index[2*E], perturb_first[N*D], perturb_last[N*D],
//         W1[D*D], b1[D], W2[D*D], b2[D]   -> out[N*D]
// ---------------------------------------------------------------------------
extern "C" void kernel_launch(void* const* d_in, const int* in_sizes, int n_in,
                              void* d_out, int out_size) {
    const float* x  = (const float*)d_in[0];
    const int*   ei = (const int*)d_in[1];
    const float* pf = (const float*)d_in[2];
    const float* pl = (const float*)d_in[3];
    const float* W1 = (const float*)d_in[4];
    const float* b1 = (const float*)d_in[5];
    const float* W2 = (const float*)d_in[6];
    const float* b2 = (const float*)d_in[7];
    float* out = (float*)d_out;

    int N = in_sizes[0] / D;
    int E = in_sizes[1] / 2;
    const int* src = ei;
    const int* dst = ei + E;

    float4* Gh; cudaGetSymbolAddress((void**)&Gh, g_h4);
    float4* Gt; cudaGetSymbolAddress((void**)&Gt, g_t4);

    int tb = 256;
    int nscan = (N + SCAN_B - 1) / SCAN_B;

    // Degrees + CSR + normalization
    zero_deg<<<(N + tb - 1) / tb, tb>>>(N);
    count_deg<<<(E + tb - 1) / tb, tb>>>(dst, E);
    scan_block_sums<<<nscan, SCAN_B>>>(N);
    scan_spine<<<1, 32>>>(nscan);
    scan_finish<<<nscan, SCAN_B>>>(N);
    fill_csr<<<(E + tb - 1) / tb, tb>>>(src, dst, E);

    int gemm_grid = (N + 127) / 128;
    int agg_grid  = (int)(((long long)N * 32 + tb - 1) / tb);

    // Layer 1: h1s = dinv * (x @ W1^T) ; t = aggregate(h1s) + b1 + pf
    gemm_nt<<<gemm_grid, tb>>>(x, W1, Gh, N);
    gather_aggregate<<<agg_grid, tb>>>(Gh, b1, (const float4*)pf, Gt, N);

    // Layer 2: h2s = dinv * (t @ W2^T) ; out = aggregate(h2s) + b2 + pl
    gemm_nt<<<gemm_grid, tb>>>((const float*)Gt, W2, Gh, N);
    gather_aggregate<<<agg_grid, tb>>>(Gh, b2, (const float4*)pl, (float4*)out, N);
}

// round 8
// speedup vs baseline: 1.9765x; 1.0394x over previous
#include <cuda_runtime.h>
#include <cuda_fp16.h>
#include <cstdint>
#include <cstring>

#define D 128
#define MAXN 100000
#define MAXE 1664000
#define SCAN_B 1024

// bit-casts (real intrinsics for these don't exist for __half2)
__device__ __forceinline__ uint32_t h2_as_u32(__half2 h) {
    uint32_t u; memcpy(&u, &h, 4); return u;
}
__device__ __forceinline__ __half2 u32_as_h2(uint32_t u) {
    __half2 h; memcpy(&h, &u, 4); return h;
}

// Scratch (allocation-free rule: __device__ globals).
__device__ uint4  g_hh[MAXN * 16];     // fp16 scaled linear output: dinv[i]*(x W^T)[i], 128 halves/row
__device__ float4 g_t4[MAXN * 32];     // layer-1 aggregated output (fp32)
__device__ int    g_deg[MAXN];
__device__ float  g_dinv[MAXN];
__device__ int    g_off[MAXN];         // CSR row start (by dst)
__device__ int    g_cur[MAXN];         // fill cursors
__device__ int    g_csrc[MAXE];        // CSR: src node per edge, grouped by dst
__device__ int    g_bsum[(MAXN + SCAN_B - 1) / SCAN_B];

// ---------------------------------------------------------------------------
// Degree histogram
// ---------------------------------------------------------------------------
__global__ void zero_deg(int n) {
    int i = blockIdx.x * blockDim.x + threadIdx.x;
    if (i < n) g_deg[i] = 0;
}

__global__ void count_deg(const int* __restrict__ dst, int E) {
    int e = blockIdx.x * blockDim.x + threadIdx.x;
    if (e < E) atomicAdd(&g_deg[dst[e]], 1);
}

// ---------------------------------------------------------------------------
// Exclusive scan of g_deg -> g_off, + dinv + cursor init
// ---------------------------------------------------------------------------
__global__ __launch_bounds__(SCAN_B)
void scan_block_sums(int n) {
    __shared__ int sh[SCAN_B];
    int i = blockIdx.x * SCAN_B + threadIdx.x;
    sh[threadIdx.x] = (i < n) ? g_deg[i] : 0;
    __syncthreads();
    for (int off = SCAN_B / 2; off > 0; off >>= 1) {
        if (threadIdx.x < off) sh[threadIdx.x] += sh[threadIdx.x + off];
        __syncthreads();
    }
    if (threadIdx.x == 0) g_bsum[blockIdx.x] = sh[0];
}

// Single warp: exclusive-scan g_bsum in place
__global__ void scan_spine(int nb) {
    int lane = threadIdx.x;
    int acc = 0;
    for (int base = 0; base < nb; base += 32) {
        int idx = base + lane;
        int orig = (idx < nb) ? g_bsum[idx] : 0;
        int v = orig;
        #pragma unroll
        for (int off = 1; off < 32; off <<= 1) {
            int t = __shfl_up_sync(0xffffffffu, v, off);
            if (lane >= off) v += t;
        }
        int tot = __shfl_sync(0xffffffffu, v, 31);
        if (idx < nb) g_bsum[idx] = v - orig + acc;
        acc += tot;
    }
}

__global__ __launch_bounds__(SCAN_B)
void scan_finish(int n) {
    __shared__ int sh[SCAN_B];
    int i = blockIdx.x * SCAN_B + threadIdx.x;
    int v = (i < n) ? g_deg[i] : 0;
    sh[threadIdx.x] = v;
    __syncthreads();
    for (int off = 1; off < SCAN_B; off <<= 1) {
        int t = (threadIdx.x >= off) ? sh[threadIdx.x - off] : 0;
        __syncthreads();
        sh[threadIdx.x] += t;
        __syncthreads();
    }
    if (i < n) {
        int excl = sh[threadIdx.x] - v + g_bsum[blockIdx.x];
        g_off[i] = excl;
        g_cur[i] = excl;
        g_dinv[i] = rsqrtf((float)(v + 1));   // +1 self-loop
    }
}

// ---------------------------------------------------------------------------
// CSR fill
// ---------------------------------------------------------------------------
__global__ void fill_csr(const int* __restrict__ src,
                         const int* __restrict__ dst, int E) {
    int e = blockIdx.x * blockDim.x + threadIdx.x;
    if (e < E) {
        int pos = atomicAdd(&g_cur[dst[e]], 1);
        g_csrc[pos] = src[e];
    }
}

// ---------------------------------------------------------------------------
// NT GEMM: H[i][j] = fp16( dinv[i] * sum_k X[i][k] * W[j][k] )
// k-major smem tiles; inner loop 4x LDS.128 + 64 FFMA per k.
// 128 rows/block, 256 threads, 8x8 register tile per thread.
// ---------------------------------------------------------------------------
__global__ __launch_bounds__(256, 2)
void gemm_nt(const float* __restrict__ X,
             const float* __restrict__ W,
             uint4* __restrict__ H,
             int M) {
    __shared__ float As[32][132];   // [k][row]
    __shared__ float Bs[32][132];   // [k][out-col]

    int tid  = threadIdx.x;
    int row0 = blockIdx.x * 128;
    int trow = tid >> 4;   // 0..15
    int tcol = tid & 15;   // 0..15

    float acc[8][8];
    #pragma unroll
    for (int i = 0; i < 8; i++)
        #pragma unroll
        for (int j = 0; j < 8; j++) acc[i][j] = 0.f;

    for (int kc = 0; kc < 4; kc++) {        // 4 chunks of 32 k
        #pragma unroll
        for (int it = 0; it < 4; it++) {
            int idx = it * 256 + tid;       // 0..1023 float4s per operand
            int r  = idx >> 3;              // 0..127 (row / out-col)
            int k4 = idx & 7;
            int grow = row0 + r;
            float4 a = make_float4(0.f, 0.f, 0.f, 0.f);
            if (grow < M)
                a = ((const float4*)(X + (size_t)grow * D + kc * 32))[k4];
            int kk = k4 * 4;
            As[kk + 0][r] = a.x; As[kk + 1][r] = a.y;
            As[kk + 2][r] = a.z; As[kk + 3][r] = a.w;
            float4 b = ((const float4*)(W + (size_t)r * D + kc * 32))[k4];
            Bs[kk + 0][r] = b.x; Bs[kk + 1][r] = b.y;
            Bs[kk + 2][r] = b.z; Bs[kk + 3][r] = b.w;
        }
        __syncthreads();

        #pragma unroll
        for (int k = 0; k < 32; k++) {
            float4 a0 = *(const float4*)&As[k][trow * 8];
            float4 a1 = *(const float4*)&As[k][trow * 8 + 4];
            float4 b0 = *(const float4*)&Bs[k][tcol * 8];
            float4 b1 = *(const float4*)&Bs[k][tcol * 8 + 4];
            float a[8] = {a0.x, a0.y, a0.z, a0.w, a1.x, a1.y, a1.z, a1.w};
            float b[8] = {b0.x, b0.y, b0.z, b0.w, b1.x, b1.y, b1.z, b1.w};
            #pragma unroll
            for (int i = 0; i < 8; i++)
                #pragma unroll
                for (int j = 0; j < 8; j++) acc[i][j] += a[i] * b[j];
        }
        __syncthreads();
    }

    #pragma unroll
    for (int i = 0; i < 8; i++) {
        int grow = row0 + trow * 8 + i;
        if (grow < M) {
            float di = g_dinv[grow];
            __half2 h0 = __float22half2_rn(make_float2(di * acc[i][0], di * acc[i][1]));
            __half2 h1 = __float22half2_rn(make_float2(di * acc[i][2], di * acc[i][3]));
            __half2 h2 = __float22half2_rn(make_float2(di * acc[i][4], di * acc[i][5]));
            __half2 h3 = __float22half2_rn(make_float2(di * acc[i][6], di * acc[i][7]));
            uint4 v;
            v.x = h2_as_u32(h0); v.y = h2_as_u32(h1);
            v.z = h2_as_u32(h2); v.w = h2_as_u32(h3);
            H[(size_t)grow * 16 + tcol] = v;   // 8 halves = 16B
        }
    }
}

// ---------------------------------------------------------------------------
// Pull-mode aggregation. h rows are fp16, pre-scaled by dinv[src]:
// out[i] = dinv[i] * ( sum_{e in CSR[i]} h[src_e] + h[i] ) + bias + pert[i]
// One warp per dst node; lane owns 4 features (uint2 = 4 halves = 8B).
// ---------------------------------------------------------------------------
__global__ __launch_bounds__(256)
void gather_aggregate(const uint2* __restrict__ h,   // [N*32] uint2 (4 halves each)
                      const float* __restrict__ bias,
                      const float4* __restrict__ pert,
                      float4* __restrict__ out,
                      int N) {
    long long t = (long long)blockIdx.x * blockDim.x + threadIdx.x;
    int i = (int)(t >> 5);
    if (i >= N) return;
    int lane = (int)(t & 31);

    int start = g_off[i];
    int deg   = g_deg[i];

    // self-loop term
    float4 acc;
    {
        uint2 u = h[(size_t)i * 32 + lane];
        float2 a = __half22float2(u32_as_h2(u.x));
        float2 b = __half22float2(u32_as_h2(u.y));
        acc = make_float4(a.x, a.y, b.x, b.y);
    }

    int j = 0;
    for (; j + 4 <= deg; j += 4) {
        int s0 = g_csrc[start + j];
        int s1 = g_csrc[start + j + 1];
        int s2 = g_csrc[start + j + 2];
        int s3 = g_csrc[start + j + 3];
        uint2 u0 = h[(size_t)s0 * 32 + lane];
        uint2 u1 = h[(size_t)s1 * 32 + lane];
        uint2 u2 = h[(size_t)s2 * 32 + lane];
        uint2 u3 = h[(size_t)s3 * 32 + lane];
        float2 a0 = __half22float2(u32_as_h2(u0.x)), b0 = __half22float2(u32_as_h2(u0.y));
        float2 a1 = __half22float2(u32_as_h2(u1.x)), b1 = __half22float2(u32_as_h2(u1.y));
        float2 a2 = __half22float2(u32_as_h2(u2.x)), b2 = __half22float2(u32_as_h2(u2.y));
        float2 a3 = __half22float2(u32_as_h2(u3.x)), b3 = __half22float2(u32_as_h2(u3.y));
        acc.x += (a0.x + a1.x) + (a2.x + a3.x);
        acc.y += (a0.y + a1.y) + (a2.y + a3.y);
        acc.z += (b0.x + b1.x) + (b2.x + b3.x);
        acc.w += (b0.y + b1.y) + (b2.y + b3.y);
    }
    for (; j < deg; j++) {
        int s0 = g_csrc[start + j];
        uint2 u0 = h[(size_t)s0 * 32 + lane];
        float2 a0 = __half22float2(u32_as_h2(u0.x));
        float2 b0 = __half22float2(u32_as_h2(u0.y));
        acc.x += a0.x; acc.y += a0.y; acc.z += b0.x; acc.w += b0.y;
    }

    float di = g_dinv[i];
    float4 bv = ((const float4*)bias)[lane];
    float4 pv = pert[(size_t)i * 32 + lane];

    out[(size_t)i * 32 + lane] = make_float4(
        di * acc.x + bv.x + pv.x,
        di * acc.y + bv.y + pv.y,
        di * acc.z + bv.z + pv.z,
        di * acc.w + bv.w + pv.w);
}

// ---------------------------------------------------------------------------
// Launch
// Inputs: x[N*D], edge_index[2*E], perturb_first[N*D], perturb_last[N*D],
//         W1[D*D], b1[D], W2[D*D], b2[D]   -> out[N*D]
// ---------------------------------------------------------------------------
extern "C" void kernel_launch(void* const* d_in, const int* in_sizes, int n_in,
                              void* d_out, int out_size) {
    const float* x  = (const float*)d_in[0];
    const int*   ei = (const int*)d_in[1];
    const float* pf = (const float*)d_in[2];
    const float* pl = (const float*)d_in[3];
    const float* W1 = (const float*)d_in[4];
    const float* b1 = (const float*)d_in[5];
    const float* W2 = (const float*)d_in[6];
    const float* b2 = (const float*)d_in[7];
    float* out = (float*)d_out;

    int N = in_sizes[0] / D;
    int E = in_sizes[1] / 2;
    const int* src = ei;
    const int* dst = ei + E;

    uint4*  Gh; cudaGetSymbolAddress((void**)&Gh, g_hh);
    float4* Gt; cudaGetSymbolAddress((void**)&Gt, g_t4);

    int tb = 256;
    int nscan = (N + SCAN_B - 1) / SCAN_B;

    // Degrees + CSR + normalization
    zero_deg<<<(N + tb - 1) / tb, tb>>>(N);
    count_deg<<<(E + tb - 1) / tb, tb>>>(dst, E);
    scan_block_sums<<<nscan, SCAN_B>>>(N);
    scan_spine<<<1, 32>>>(nscan);
    scan_finish<<<nscan, SCAN_B>>>(N);
    fill_csr<<<(E + tb - 1) / tb, tb>>>(src, dst, E);

    int gemm_grid = (N + 127) / 128;
    int agg_grid  = (int)(((long long)N * 32 + tb - 1) / tb);

    // Layer 1: h1 = fp16(dinv * (x @ W1^T)) ; t = aggregate(h1) + b1 + pf
    gemm_nt<<<gemm_grid, tb>>>(x, W1, Gh, N);
    gather_aggregate<<<agg_grid, tb>>>((const uint2*)Gh, b1, (const float4*)pf, Gt, N);

    // Layer 2: h2 = fp16(dinv * (t @ W2^T)) ; out = aggregate(h2) + b2 + pl
    gemm_nt<<<gemm_grid, tb>>>((const float*)Gt, W2, Gh, N);
    gather_aggregate<<<agg_grid, tb>>>((const uint2*)Gh, b2, (const float4*)pl, (float4*)out, N);
}